// round 14
// baseline (speedup 1.0000x reference)
#include <cuda_runtime.h>
#include <cuda_fp16.h>
#include <cstdint>

#define TT 1024
#define BB 32
#define HD 512
#define NG 1536           // 3*HD
#define MM (TT*BB)        // 32768

#define SCAN_CTAS 64
#define GEMM_CTAS 84
#define GRID (SCAN_CTAS + GEMM_CTAS)   // 148 <= SM count -> 1 CTA/SM, co-resident
#define NTILES 12                       // NG/128
#define MTILES 256                      // MM/128
#define TOTAL_TICKETS (2 * MTILES * NTILES)

typedef unsigned long long ull;

// ---------------- device scratch (no allocations allowed) ----------------
__device__ float g_gi0[(size_t)MM * NG];     // forward gi
__device__ float g_gi1[(size_t)MM * NG];     // backward gi
__device__ float g_buf0[(size_t)MM * 1024];  // layer0 output
__device__ float g_buf1[(size_t)MM * 1024];  // layer1 output
__device__ __half g_h16[2][2][BB * HD];      // ping-pong h per direction (fp16 exchange)
__device__ unsigned g_cnt4[4 * 32];          // 4 group barrier counters (128B apart)
__device__ unsigned g_ticket;                // gemm tile ticket
__device__ unsigned g_gflag[2][MTILES];      // per (dir, m-band) completed N-tiles (ready at 12)

// ========================= common helpers =========================
__device__ __forceinline__ unsigned pack2(float a, float b) {
    __half2 h = __floats2half2_rn(a, b);
    return *(unsigned*)&h;
}
__device__ __forceinline__ void mma16(float* d, const unsigned* a, const unsigned* b) {
    asm volatile("mma.sync.aligned.m16n8k16.row.col.f32.f16.f16.f32 "
                 "{%0,%1,%2,%3}, {%4,%5,%6,%7}, {%8,%9}, {%0,%1,%2,%3};"
                 : "+f"(d[0]), "+f"(d[1]), "+f"(d[2]), "+f"(d[3])
                 : "r"(a[0]), "r"(a[1]), "r"(a[2]), "r"(a[3]), "r"(b[0]), "r"(b[1]));
}
#define LDSM_X4(r0, r1, r2, r3, addr)                                            \
    asm volatile("ldmatrix.sync.aligned.m8n8.x4.shared.b16 {%0,%1,%2,%3}, [%4];" \
                 : "=r"(r0), "=r"(r1), "=r"(r2), "=r"(r3) : "r"(addr))
__device__ __forceinline__ float sigm(float x) { return 1.f / (1.f + __expf(-x)); }
__device__ __forceinline__ unsigned ld_acq(const unsigned* p) {
    unsigned v;
    asm volatile("ld.acquire.gpu.global.u32 %0, [%1];" : "=r"(v) : "l"(p) : "memory");
    return v;
}

#define SSH 40            // gemm smem halfs per row
#define HS 520            // scan h16 halfs per row (512 + 8 pad)
#define POOL_BYTES 43520

// =====================================================================
// FUSED layer kernel: bid < 64 -> scan consumer; bid >= 64 -> gemm producer
// =====================================================================
__global__ __launch_bounds__(512, 1) void fused_layer(
    const float* __restrict__ A,
    const float* __restrict__ W0, const float* __restrict__ W1,
    const float* __restrict__ bi0, const float* __restrict__ bi1,
    const float* __restrict__ whhF, const float* __restrict__ whhB,
    const float* __restrict__ bhhF, const float* __restrict__ bhhB,
    const float* __restrict__ h0F,  const float* __restrict__ h0B,
    float* __restrict__ gi0, float* __restrict__ gi1,
    float* __restrict__ out, float* __restrict__ finF, float* __restrict__ finB,
    int K)
{
    extern __shared__ char pool[];
    int bid = blockIdx.x;
    int tid = threadIdx.x, w = tid >> 5, lane = tid & 31;
    int g = lane >> 2, t = lane & 3;

    if (bid >= SCAN_CTAS) {
        // ==================== GEMM producer ====================
        if (tid >= 256) return;
        __half* sAB   = (__half*)pool;                       // [2][2][128*SSH]
        float*  sbias = (float*)(pool + 4 * 128 * SSH * 2);  // 128 floats
        unsigned* tick_s = (unsigned*)(pool + 4 * 128 * SSH * 2 + 512);

        int warp = w;
        int wm = (warp & 3) * 32;
        int wn = (warp >> 2) * 64;
        int grow = tid >> 1, gcol = (tid & 1) * 16;

        uint32_t a_off = (uint32_t)(((wm + (lane & 15)) * SSH + (lane >> 4) * 8) * 2);
        uint32_t b_off = (uint32_t)(((wn + (((lane >> 3) >= 2) ? 8 : 0) + (lane & 7)) * SSH
                                    + ((lane >> 3) & 1) * 8) * 2);
        int kT = K / 32;

        for (;;) {
            __syncthreads();            // protect smem across iterations
            if (tid == 0) *tick_s = atomicAdd(&g_ticket, 1u);
            __syncthreads();
            unsigned k = *tick_s;
            if (k >= TOTAL_TICKETS) break;
            int q = k / 24, r = k % 24;
            int dz, mt, nt;
            if (r < NTILES) { dz = 0; mt = q;              nt = r; }
            else            { dz = 1; mt = MTILES - 1 - q; nt = r - NTILES; }
            const float* W    = dz ? W1  : W0;
            const float* bias = dz ? bi1 : bi0;
            float*       C    = dz ? gi1 : gi0;
            int m0 = mt * 128, n0 = nt * 128;

            if (tid < 128) sbias[tid] = bias[n0 + tid];

            const float* Ag = A + (size_t)(m0 + grow) * K + gcol;
            const float* Wg = W + (size_t)(n0 + grow) * K + gcol;

            float acc[2][8][4];
#pragma unroll
            for (int mtt = 0; mtt < 2; mtt++)
#pragma unroll
                for (int ntt = 0; ntt < 8; ntt++)
#pragma unroll
                    for (int e = 0; e < 4; e++) acc[mtt][ntt][e] = 0.f;

            float4 av[4], wv[4];
#pragma unroll
            for (int qq = 0; qq < 4; qq++) { av[qq] = *(const float4*)(Ag + qq * 4); wv[qq] = *(const float4*)(Wg + qq * 4); }
            {
                __half* dA = sAB + 0 * 128 * SSH;
                __half* dB = sAB + 1 * 128 * SSH;
                uint4 ua0 = { pack2(av[0].x, av[0].y), pack2(av[0].z, av[0].w), pack2(av[1].x, av[1].y), pack2(av[1].z, av[1].w) };
                uint4 ua1 = { pack2(av[2].x, av[2].y), pack2(av[2].z, av[2].w), pack2(av[3].x, av[3].y), pack2(av[3].z, av[3].w) };
                uint4 uw0 = { pack2(wv[0].x, wv[0].y), pack2(wv[0].z, wv[0].w), pack2(wv[1].x, wv[1].y), pack2(wv[1].z, wv[1].w) };
                uint4 uw1 = { pack2(wv[2].x, wv[2].y), pack2(wv[2].z, wv[2].w), pack2(wv[3].x, wv[3].y), pack2(wv[3].z, wv[3].w) };
                *(uint4*)&dA[grow * SSH + gcol]     = ua0;
                *(uint4*)&dA[grow * SSH + gcol + 8] = ua1;
                *(uint4*)&dB[grow * SSH + gcol]     = uw0;
                *(uint4*)&dB[grow * SSH + gcol + 8] = uw1;
            }
            __syncthreads();

            for (int s = 0; s < kT; s++) {
                int bb = s & 1;
                if (s + 1 < kT) {
                    int k0 = (s + 1) * 32;
#pragma unroll
                    for (int qq = 0; qq < 4; qq++) {
                        av[qq] = *(const float4*)(Ag + k0 + qq * 4);
                        wv[qq] = *(const float4*)(Wg + k0 + qq * 4);
                    }
                }
                uint32_t a_u = (uint32_t)__cvta_generic_to_shared(sAB + (bb * 2 + 0) * 128 * SSH) + a_off;
                uint32_t b_u = (uint32_t)__cvta_generic_to_shared(sAB + (bb * 2 + 1) * 128 * SSH) + b_off;
#pragma unroll
                for (int kk = 0; kk < 2; kk++) {
                    uint32_t kb = (uint32_t)(kk * 32);
                    unsigned afr[2][4], bfr[8][2];
                    LDSM_X4(afr[0][0], afr[0][1], afr[0][2], afr[0][3], a_u + kb);
                    LDSM_X4(afr[1][0], afr[1][1], afr[1][2], afr[1][3], a_u + 16 * SSH * 2 + kb);
#pragma unroll
                    for (int qq = 0; qq < 4; qq++)
                        LDSM_X4(bfr[2 * qq][0], bfr[2 * qq][1], bfr[2 * qq + 1][0], bfr[2 * qq + 1][1],
                                b_u + qq * 16 * SSH * 2 + kb);
#pragma unroll
                    for (int mtt = 0; mtt < 2; mtt++)
#pragma unroll
                        for (int ntt = 0; ntt < 8; ntt++)
                            mma16(acc[mtt][ntt], afr[mtt], bfr[ntt]);
                }
                if (s + 1 < kT) {
                    int nb = bb ^ 1;
                    __half* dA = sAB + (nb * 2 + 0) * 128 * SSH;
                    __half* dB = sAB + (nb * 2 + 1) * 128 * SSH;
                    uint4 ua0 = { pack2(av[0].x, av[0].y), pack2(av[0].z, av[0].w), pack2(av[1].x, av[1].y), pack2(av[1].z, av[1].w) };
                    uint4 ua1 = { pack2(av[2].x, av[2].y), pack2(av[2].z, av[2].w), pack2(av[3].x, av[3].y), pack2(av[3].z, av[3].w) };
                    uint4 uw0 = { pack2(wv[0].x, wv[0].y), pack2(wv[0].z, wv[0].w), pack2(wv[1].x, wv[1].y), pack2(wv[1].z, wv[1].w) };
                    uint4 uw1 = { pack2(wv[2].x, wv[2].y), pack2(wv[2].z, wv[2].w), pack2(wv[3].x, wv[3].y), pack2(wv[3].z, wv[3].w) };
                    *(uint4*)&dA[grow * SSH + gcol]     = ua0;
                    *(uint4*)&dA[grow * SSH + gcol + 8] = ua1;
                    *(uint4*)&dB[grow * SSH + gcol]     = uw0;
                    *(uint4*)&dB[grow * SSH + gcol + 8] = uw1;
                }
                __syncthreads();
            }

#pragma unroll
            for (int mtt = 0; mtt < 2; mtt++) {
                int m = m0 + wm + mtt * 16 + g;
#pragma unroll
                for (int ntt = 0; ntt < 8; ntt++) {
                    int nl = wn + ntt * 8 + 2 * t;
                    float b0 = sbias[nl], b1 = sbias[nl + 1];
                    float2 v0 = { acc[mtt][ntt][0] + b0, acc[mtt][ntt][1] + b1 };
                    float2 v1 = { acc[mtt][ntt][2] + b0, acc[mtt][ntt][3] + b1 };
                    *(float2*)&C[(size_t)m * NG + n0 + nl]       = v0;
                    *(float2*)&C[(size_t)(m + 8) * NG + n0 + nl] = v1;
                }
            }
            // release-RED: orders the gi stores above before the flag increment
            if (tid == 0) {
                __threadfence();
                atomicAdd(&g_gflag[dz][mt], 1u);
            } else {
                __threadfence();   // all threads' stores must be visible before CTA's flag;
            }                      // fence by every thread, single flag add by tid0
        }
        return;
    }

    // ==================== SCAN consumer ====================
    __half* h16 = (__half*)pool;                 // 16 x HS
    float*  sg  = (float*)(pool + 16 * HS * 2);  // [3][16][34]

    int dir = bid >> 5, cid = bid & 31, bhalf = cid & 1, jblk = cid >> 1;
    unsigned* cnt = &g_cnt4[(dir * 2 + bhalf) * 32];

    const float* gi  = dir ? gi1  : gi0;
    const float* whh = dir ? whhB : whhF;
    const float* bhh = dir ? bhhB : bhhF;
    const float* h0  = dir ? h0B  : h0F;
    float* fin = dir ? finB : finF;

    int eb = tid >> 5, ejj = tid & 31;           // (batch 0-15, local j 0-31)
    int ej  = jblk * 32 + ejj;
    int ebl = bhalf * 16 + eb;
    float bhr = bhh[ej], bhz = bhh[HD + ej], bhn = bhh[2 * HD + ej];
    float hp = __ldcg(&h0[(size_t)ebl * HD + ej]);

    unsigned bw[32][2];
    if (w < 12) {
        int nl = w * 8 + g;
        int gate = nl >> 5, jj = nl & 31;
        const float* Wr = whh + (size_t)(gate * HD + jblk * 32 + jj) * HD;
#pragma unroll
        for (int kk = 0; kk < 32; kk++) {
            int k0 = kk * 16;
            bw[kk][0] = pack2(Wr[k0 + 2 * t],     Wr[k0 + 2 * t + 1]);
            bw[kk][1] = pack2(Wr[k0 + 2 * t + 8], Wr[k0 + 2 * t + 9]);
        }
    }

    uint32_t h16a = (uint32_t)__cvta_generic_to_shared(h16);
    uint32_t lma = h16a + (uint32_t)(((lane & 15) * HS + (lane >> 4) * 8) * 2);

    // pre-loop: wait gi bands for steps 0 and 1
    if (tid == 0) {
        int ta = dir ? (TT - 1) : 0;
        int tb = dir ? (TT - 2) : 1;
        while (ld_acq(&g_gflag[dir][ta >> 2]) < 12u) {}
        while (ld_acq(&g_gflag[dir][tb >> 2]) < 12u) {}
    }
    __syncthreads();

    float gir, giz, gin;
    {
        int t0 = dir ? (TT - 1) : 0;
        size_t gb = ((size_t)t0 * BB + ebl) * NG;
        gir = __ldcg(&gi[gb + ej]);
        giz = __ldcg(&gi[gb + HD + ej]);
        gin = __ldcg(&gi[gb + 2 * HD + ej]);
    }

    for (int s = 0; s < TT; s++) {
        int tt = dir ? (TT - 1 - s) : s;

        // ---- stage h (16 b x 512 fp16) ----
        if (s == 0) {
            const float4* src = (const float4*)(h0 + (size_t)ebl * HD + ejj * 16);
            float4 v0 = __ldcg(src + 0), v1 = __ldcg(src + 1), v2 = __ldcg(src + 2), v3 = __ldcg(src + 3);
            uint4 u0 = { pack2(v0.x, v0.y), pack2(v0.z, v0.w), pack2(v1.x, v1.y), pack2(v1.z, v1.w) };
            uint4 u1 = { pack2(v2.x, v2.y), pack2(v2.z, v2.w), pack2(v3.x, v3.y), pack2(v3.z, v3.w) };
            *(uint4*)&h16[eb * HS + ejj * 16]     = u0;
            *(uint4*)&h16[eb * HS + ejj * 16 + 8] = u1;
        } else {
            const uint4* src = (const uint4*)(g_h16[dir][s & 1] + (size_t)ebl * HD);
            *(uint4*)&h16[eb * HS + ejj * 8]        = __ldcg(src + ejj);
            *(uint4*)&h16[eb * HS + (ejj + 32) * 8] = __ldcg(src + ejj + 32);
        }
        __syncthreads();

        // ---- recurrent GEMM: 12 warps x (32 ldmatrix + 32 mma) ----
        if (w < 12) {
            float acc[4] = { 0.f, 0.f, 0.f, 0.f };
#pragma unroll
            for (int kk = 0; kk < 32; kk++) {
                unsigned a0, a1, a2, a3;
                LDSM_X4(a0, a1, a2, a3, lma + kk * 32);
                unsigned af[4] = { a0, a1, a2, a3 };
                mma16(acc, af, bw[kk]);
            }
            int nl = w * 8 + 2 * t;
            int gate = nl >> 5, jj2 = nl & 31;
            float* p = &sg[gate * 544 + g * 34 + jj2];
            *(float2*)p            = make_float2(acc[0], acc[1]);
            *(float2*)(p + 8 * 34) = make_float2(acc[2], acc[3]);
        }
        __syncthreads();

        // issue next-step gi prefetch FIRST so its latency overlaps gate math
        float pr, pz, pn;
        {
            int s2 = (s + 1 < TT) ? (s + 1) : s;
            int t2 = dir ? (TT - 1 - s2) : s2;
            size_t gb = ((size_t)t2 * BB + ebl) * NG;
            pr = __ldcg(&gi[gb + ej]);
            pz = __ldcg(&gi[gb + HD + ej]);
            pn = __ldcg(&gi[gb + 2 * HD + ej]);
        }

        // ---- gate math (1 thread = 1 (b,j)) ----
        float gr = sg[0 * 544 + eb * 34 + ejj];
        float gz = sg[1 * 544 + eb * 34 + ejj];
        float gn = sg[2 * 544 + eb * 34 + ejj];
        float r  = sigm(gir + gr + bhr);
        float z  = sigm(giz + gz + bhz);
        float n  = tanhf(gin + r * (gn + bhn));
        float hn = (1.f - z) * n + z * hp;
        hp = hn;
        gir = pr; giz = pz; gin = pn;

        // publish h (fp16)
        g_h16[dir][(s + 1) & 1][(size_t)ebl * HD + ej] = __float2half_rn(hn);

        // ---- barrier: release-RED arrive + spin (tid0) | gi-band poll (tid32, overlapped) ----
        __syncthreads();
        if (tid == 0) {
            asm volatile("red.release.gpu.global.add.u32 [%0], %1;"
                         :: "l"(cnt), "r"(1u) : "memory");
            unsigned target = (unsigned)(s + 1) * 16u;
            while (ld_acq(cnt) < target) {}
        } else if (tid == 32) {
            int s3 = (s + 2 < TT) ? (s + 2) : (TT - 1);
            if ((s3 & 3) == 0) {                     // gi band changes only every 4 steps
                int t3 = dir ? (TT - 1 - s3) : s3;
                while (ld_acq(&g_gflag[dir][t3 >> 2]) < 12u) {}
            }
        }
        __syncthreads();

        // off-critical-path output stores
        out[((size_t)tt * BB + ebl) * 1024 + dir * HD + ej] = hn;
        if (s == TT - 1) fin[(size_t)ebl * HD + ej] = hn;
    }
}

__global__ void reset_cnt() {
    if (threadIdx.x < 128) g_cnt4[threadIdx.x] = 0u;
    if (threadIdx.x == 0) g_ticket = 0u;
    unsigned* f = &g_gflag[0][0];
    for (int i = threadIdx.x; i < 2 * MTILES; i += blockDim.x) f[i] = 0u;
}

// ========================= host launcher =========================
extern "C" void kernel_launch(void* const* d_in, const int* in_sizes, int n_in,
                              void* d_out, int out_size)
{
    (void)in_sizes; (void)n_in; (void)out_size;
    const float* x  = (const float*)d_in[0];
    const float* h0 = (const float*)d_in[1];
    float* out    = (float*)d_out;
    float* finals = out + (size_t)TT * BB * 1024;

    float *gi0, *gi1, *buf0, *buf1;
    cudaGetSymbolAddress((void**)&gi0,  g_gi0);
    cudaGetSymbolAddress((void**)&gi1,  g_gi1);
    cudaGetSymbolAddress((void**)&buf0, g_buf0);
    cudaGetSymbolAddress((void**)&buf1, g_buf1);

    const float* layin[3]   = { x, buf0, buf1 };
    float*       layout_[3] = { buf0, buf1, out };
    int Ks[3] = { 256, 1024, 1024 };

    for (int L = 0; L < 3; L++) {
        const float* wih  = (const float*)d_in[2 + L * 8 + 0];
        const float* whh  = (const float*)d_in[2 + L * 8 + 1];
        const float* bih  = (const float*)d_in[2 + L * 8 + 2];
        const float* bhh  = (const float*)d_in[2 + L * 8 + 3];
        const float* wihr = (const float*)d_in[2 + L * 8 + 4];
        const float* whhr = (const float*)d_in[2 + L * 8 + 5];
        const float* bihr = (const float*)d_in[2 + L * 8 + 6];
        const float* bhhr = (const float*)d_in[2 + L * 8 + 7];

        reset_cnt<<<1, 256>>>();
        fused_layer<<<GRID, 512, POOL_BYTES>>>(
            layin[L], wih, wihr, bih, bihr,
            whh, whhr, bhh, bhhr,
            h0 + (size_t)(2 * L) * BB * HD,
            h0 + (size_t)(2 * L + 1) * BB * HD,
            gi0, gi1,
            layout_[L],
            finals + (size_t)(2 * L) * BB * HD,
            finals + (size_t)(2 * L + 1) * BB * HD,
            Ks[L]);
    }
}

// round 15
// speedup vs baseline: 1.0529x; 1.0529x over previous
#include <cuda_runtime.h>
#include <cuda_fp16.h>
#include <cstdint>

#define TT 1024
#define BB 32
#define HD 512
#define NG 1536           // 3*HD
#define MM (TT*BB)        // 32768

#define SCAN_CTAS 64
#define GEMM_CTAS 84
#define GRID (SCAN_CTAS + GEMM_CTAS)   // 148 <= SM count -> 1 CTA/SM, co-resident
#define NTILES 12                       // NG/128
#define MTILES 256                      // MM/128
#define TOTAL_TICKETS (2 * MTILES * NTILES)

typedef unsigned long long ull;

// ---------------- device scratch (no allocations allowed) ----------------
__device__ float g_gi0[(size_t)MM * NG];     // forward gi
__device__ float g_gi1[(size_t)MM * NG];     // backward gi
__device__ float g_buf0[(size_t)MM * 1024];  // layer0 output
__device__ float g_buf1[(size_t)MM * 1024];  // layer1 output
__device__ __half g_h16[2][2][BB * HD];      // ping-pong h per direction (fp16 exchange)
__device__ unsigned g_cnt4[4 * 32];          // 4 group barrier counters (128B apart)
__device__ unsigned g_ticket;                // gemm tile ticket
__device__ unsigned g_gflag[2][MTILES];      // per (dir, m-band) completed N-tiles (ready at 12)

// ========================= common helpers =========================
__device__ __forceinline__ unsigned pack2(float a, float b) {
    __half2 h = __floats2half2_rn(a, b);
    return *(unsigned*)&h;
}
__device__ __forceinline__ void mma16(float* d, const unsigned* a, const unsigned* b) {
    asm volatile("mma.sync.aligned.m16n8k16.row.col.f32.f16.f16.f32 "
                 "{%0,%1,%2,%3}, {%4,%5,%6,%7}, {%8,%9}, {%0,%1,%2,%3};"
                 : "+f"(d[0]), "+f"(d[1]), "+f"(d[2]), "+f"(d[3])
                 : "r"(a[0]), "r"(a[1]), "r"(a[2]), "r"(a[3]), "r"(b[0]), "r"(b[1]));
}
#define LDSM_X4(r0, r1, r2, r3, addr)                                            \
    asm volatile("ldmatrix.sync.aligned.m8n8.x4.shared.b16 {%0,%1,%2,%3}, [%4];" \
                 : "=r"(r0), "=r"(r1), "=r"(r2), "=r"(r3) : "r"(addr))
__device__ __forceinline__ float sigm(float x) { return 1.f / (1.f + __expf(-x)); }
__device__ __forceinline__ unsigned ld_acq(const unsigned* p) {
    unsigned v;
    asm volatile("ld.acquire.gpu.global.u32 %0, [%1];" : "=r"(v) : "l"(p) : "memory");
    return v;
}

#define SSH 40            // gemm smem halfs per row
#define HS 520            // scan h16 halfs per row (512 + 8 pad)
#define POOL_BYTES 43520

// =====================================================================
// FUSED layer kernel: bid < 64 -> scan consumer; bid >= 64 -> gemm producer
// =====================================================================
__global__ __launch_bounds__(512, 1) void fused_layer(
    const float* __restrict__ A,
    const float* __restrict__ W0, const float* __restrict__ W1,
    const float* __restrict__ bi0, const float* __restrict__ bi1,
    const float* __restrict__ whhF, const float* __restrict__ whhB,
    const float* __restrict__ bhhF, const float* __restrict__ bhhB,
    const float* __restrict__ h0F,  const float* __restrict__ h0B,
    float* __restrict__ gi0, float* __restrict__ gi1,
    float* __restrict__ out, float* __restrict__ finF, float* __restrict__ finB,
    int K)
{
    extern __shared__ char pool[];
    int bid = blockIdx.x;
    int tid = threadIdx.x, w = tid >> 5, lane = tid & 31;
    int g = lane >> 2, t = lane & 3;

    if (bid >= SCAN_CTAS) {
        // ==================== GEMM producer (ALL 512 threads, 16 warps 4m x 4n) ====================
        __half* sAB   = (__half*)pool;                       // [2][2][128*SSH]
        float*  sbias = (float*)(pool + 4 * 128 * SSH * 2);  // 128 floats
        unsigned* tick_s = (unsigned*)(pool + 4 * 128 * SSH * 2 + 512);

        int wm = (w & 3) * 32;         // warp M offset
        int wn = (w >> 2) * 32;        // warp N offset
        int grow = tid >> 2, gcol = (tid & 3) * 8;   // 512 thr: 8 floats of A and B each

        uint32_t a_off = (uint32_t)(((wm + (lane & 15)) * SSH + (lane >> 4) * 8) * 2);
        uint32_t b_off = (uint32_t)(((wn + (((lane >> 3) >= 2) ? 8 : 0) + (lane & 7)) * SSH
                                    + ((lane >> 3) & 1) * 8) * 2);
        int kT = K / 32;

        for (;;) {
            __syncthreads();            // protect smem across iterations
            if (tid == 0) *tick_s = atomicAdd(&g_ticket, 1u);
            __syncthreads();
            unsigned k = *tick_s;
            if (k >= TOTAL_TICKETS) break;
            int q = k / 24, r = k % 24;
            int dz, mt, nt;
            if (r < NTILES) { dz = 0; mt = q;              nt = r; }
            else            { dz = 1; mt = MTILES - 1 - q; nt = r - NTILES; }
            const float* W    = dz ? W1  : W0;
            const float* bias = dz ? bi1 : bi0;
            float*       C    = dz ? gi1 : gi0;
            int m0 = mt * 128, n0 = nt * 128;

            if (tid < 128) sbias[tid] = bias[n0 + tid];

            const float* Ag = A + (size_t)(m0 + grow) * K + gcol;
            const float* Wg = W + (size_t)(n0 + grow) * K + gcol;

            float acc[2][4][4];
#pragma unroll
            for (int mtt = 0; mtt < 2; mtt++)
#pragma unroll
                for (int ntt = 0; ntt < 4; ntt++)
#pragma unroll
                    for (int e = 0; e < 4; e++) acc[mtt][ntt][e] = 0.f;

            float4 av0, av1, wv0, wv1;
            av0 = *(const float4*)(Ag);     av1 = *(const float4*)(Ag + 4);
            wv0 = *(const float4*)(Wg);     wv1 = *(const float4*)(Wg + 4);
            {
                __half* dA = sAB + 0 * 128 * SSH;
                __half* dB = sAB + 1 * 128 * SSH;
                uint4 ua = { pack2(av0.x, av0.y), pack2(av0.z, av0.w), pack2(av1.x, av1.y), pack2(av1.z, av1.w) };
                uint4 uw = { pack2(wv0.x, wv0.y), pack2(wv0.z, wv0.w), pack2(wv1.x, wv1.y), pack2(wv1.z, wv1.w) };
                *(uint4*)&dA[grow * SSH + gcol] = ua;
                *(uint4*)&dB[grow * SSH + gcol] = uw;
            }
            __syncthreads();

            for (int s = 0; s < kT; s++) {
                int bb = s & 1;
                if (s + 1 < kT) {
                    int k0 = (s + 1) * 32;
                    av0 = *(const float4*)(Ag + k0);     av1 = *(const float4*)(Ag + k0 + 4);
                    wv0 = *(const float4*)(Wg + k0);     wv1 = *(const float4*)(Wg + k0 + 4);
                }
                uint32_t a_u = (uint32_t)__cvta_generic_to_shared(sAB + (bb * 2 + 0) * 128 * SSH) + a_off;
                uint32_t b_u = (uint32_t)__cvta_generic_to_shared(sAB + (bb * 2 + 1) * 128 * SSH) + b_off;
#pragma unroll
                for (int kk = 0; kk < 2; kk++) {
                    uint32_t kb = (uint32_t)(kk * 32);
                    unsigned afr[2][4], bfr[4][2];
                    LDSM_X4(afr[0][0], afr[0][1], afr[0][2], afr[0][3], a_u + kb);
                    LDSM_X4(afr[1][0], afr[1][1], afr[1][2], afr[1][3], a_u + 16 * SSH * 2 + kb);
                    LDSM_X4(bfr[0][0], bfr[0][1], bfr[1][0], bfr[1][1], b_u + kb);
                    LDSM_X4(bfr[2][0], bfr[2][1], bfr[3][0], bfr[3][1], b_u + 16 * SSH * 2 + kb);
#pragma unroll
                    for (int mtt = 0; mtt < 2; mtt++)
#pragma unroll
                        for (int ntt = 0; ntt < 4; ntt++)
                            mma16(acc[mtt][ntt], afr[mtt], bfr[ntt]);
                }
                if (s + 1 < kT) {
                    int nb = bb ^ 1;
                    __half* dA = sAB + (nb * 2 + 0) * 128 * SSH;
                    __half* dB = sAB + (nb * 2 + 1) * 128 * SSH;
                    uint4 ua = { pack2(av0.x, av0.y), pack2(av0.z, av0.w), pack2(av1.x, av1.y), pack2(av1.z, av1.w) };
                    uint4 uw = { pack2(wv0.x, wv0.y), pack2(wv0.z, wv0.w), pack2(wv1.x, wv1.y), pack2(wv1.z, wv1.w) };
                    *(uint4*)&dA[grow * SSH + gcol] = ua;
                    *(uint4*)&dB[grow * SSH + gcol] = uw;
                }
                __syncthreads();
            }

#pragma unroll
            for (int mtt = 0; mtt < 2; mtt++) {
                int m = m0 + wm + mtt * 16 + g;
#pragma unroll
                for (int ntt = 0; ntt < 4; ntt++) {
                    int nl = wn + ntt * 8 + 2 * t;
                    float b0 = sbias[nl], b1 = sbias[nl + 1];
                    float2 v0 = { acc[mtt][ntt][0] + b0, acc[mtt][ntt][1] + b1 };
                    float2 v1 = { acc[mtt][ntt][2] + b0, acc[mtt][ntt][3] + b1 };
                    *(float2*)&C[(size_t)m * NG + n0 + nl]       = v0;
                    *(float2*)&C[(size_t)(m + 8) * NG + n0 + nl] = v1;
                }
            }
            __threadfence();                     // make gi stores visible before flag
            if (tid == 0) atomicAdd(&g_gflag[dz][mt], 1u);
        }
        return;
    }

    // ==================== SCAN consumer (R13 verbatim) ====================
    __half* h16 = (__half*)pool;                 // 16 x HS
    float*  sg  = (float*)(pool + 16 * HS * 2);  // [3][16][34]

    int dir = bid >> 5, cid = bid & 31, bhalf = cid & 1, jblk = cid >> 1;
    unsigned* cnt = &g_cnt4[(dir * 2 + bhalf) * 32];

    const float* gi  = dir ? gi1  : gi0;
    const float* whh = dir ? whhB : whhF;
    const float* bhh = dir ? bhhB : bhhF;
    const float* h0  = dir ? h0B  : h0F;
    float* fin = dir ? finB : finF;

    int eb = tid >> 5, ejj = tid & 31;           // (batch 0-15, local j 0-31)
    int ej  = jblk * 32 + ejj;
    int ebl = bhalf * 16 + eb;
    float bhr = bhh[ej], bhz = bhh[HD + ej], bhn = bhh[2 * HD + ej];
    float hp = __ldcg(&h0[(size_t)ebl * HD + ej]);

    unsigned bw[32][2];
    if (w < 12) {
        int nl = w * 8 + g;
        int gate = nl >> 5, jj = nl & 31;
        const float* Wr = whh + (size_t)(gate * HD + jblk * 32 + jj) * HD;
#pragma unroll
        for (int kk = 0; kk < 32; kk++) {
            int k0 = kk * 16;
            bw[kk][0] = pack2(Wr[k0 + 2 * t],     Wr[k0 + 2 * t + 1]);
            bw[kk][1] = pack2(Wr[k0 + 2 * t + 8], Wr[k0 + 2 * t + 9]);
        }
    }

    uint32_t h16a = (uint32_t)__cvta_generic_to_shared(h16);
    uint32_t lma = h16a + (uint32_t)(((lane & 15) * HS + (lane >> 4) * 8) * 2);

    // pre-loop: wait gi bands for steps 0 and 1
    if (tid == 0) {
        int ta = dir ? (TT - 1) : 0;
        int tb = dir ? (TT - 2) : 1;
        while (ld_acq(&g_gflag[dir][ta >> 2]) < 12u) {}
        while (ld_acq(&g_gflag[dir][tb >> 2]) < 12u) {}
    }
    __syncthreads();

    float gir, giz, gin;
    {
        int t0 = dir ? (TT - 1) : 0;
        size_t gb = ((size_t)t0 * BB + ebl) * NG;
        gir = __ldcg(&gi[gb + ej]);
        giz = __ldcg(&gi[gb + HD + ej]);
        gin = __ldcg(&gi[gb + 2 * HD + ej]);
    }

    for (int s = 0; s < TT; s++) {
        int tt = dir ? (TT - 1 - s) : s;

        // ---- stage h (16 b x 512 fp16) ----
        if (s == 0) {
            const float4* src = (const float4*)(h0 + (size_t)ebl * HD + ejj * 16);
            float4 v0 = __ldcg(src + 0), v1 = __ldcg(src + 1), v2 = __ldcg(src + 2), v3 = __ldcg(src + 3);
            uint4 u0 = { pack2(v0.x, v0.y), pack2(v0.z, v0.w), pack2(v1.x, v1.y), pack2(v1.z, v1.w) };
            uint4 u1 = { pack2(v2.x, v2.y), pack2(v2.z, v2.w), pack2(v3.x, v3.y), pack2(v3.z, v3.w) };
            *(uint4*)&h16[eb * HS + ejj * 16]     = u0;
            *(uint4*)&h16[eb * HS + ejj * 16 + 8] = u1;
        } else {
            const uint4* src = (const uint4*)(g_h16[dir][s & 1] + (size_t)ebl * HD);
            *(uint4*)&h16[eb * HS + ejj * 8]        = __ldcg(src + ejj);
            *(uint4*)&h16[eb * HS + (ejj + 32) * 8] = __ldcg(src + ejj + 32);
        }
        __syncthreads();

        // ---- recurrent GEMM: 12 warps x (32 ldmatrix + 32 mma) ----
        if (w < 12) {
            float acc[4] = { 0.f, 0.f, 0.f, 0.f };
#pragma unroll
            for (int kk = 0; kk < 32; kk++) {
                unsigned a0, a1, a2, a3;
                LDSM_X4(a0, a1, a2, a3, lma + kk * 32);
                unsigned af[4] = { a0, a1, a2, a3 };
                mma16(acc, af, bw[kk]);
            }
            int nl = w * 8 + 2 * t;
            int gate = nl >> 5, jj2 = nl & 31;
            float* p = &sg[gate * 544 + g * 34 + jj2];
            *(float2*)p            = make_float2(acc[0], acc[1]);
            *(float2*)(p + 8 * 34) = make_float2(acc[2], acc[3]);
        }
        __syncthreads();

        // ---- gate math (1 thread = 1 (b,j)) ----
        float gr = sg[0 * 544 + eb * 34 + ejj];
        float gz = sg[1 * 544 + eb * 34 + ejj];
        float gn = sg[2 * 544 + eb * 34 + ejj];
        float r  = sigm(gir + gr + bhr);
        float z  = sigm(giz + gz + bhz);
        float n  = tanhf(gin + r * (gn + bhn));
        float hn = (1.f - z) * n + z * hp;
        hp = hn;

        // publish h (fp16)
        g_h16[dir][(s + 1) & 1][(size_t)ebl * HD + ej] = __float2half_rn(hn);

        // prefetch next gi (readiness ensured one step ago)
        {
            int s2 = (s + 1 < TT) ? (s + 1) : s;
            int t2 = dir ? (TT - 1 - s2) : s2;
            size_t gb = ((size_t)t2 * BB + ebl) * NG;
            gir = __ldcg(&gi[gb + ej]);
            giz = __ldcg(&gi[gb + HD + ej]);
            gin = __ldcg(&gi[gb + 2 * HD + ej]);
        }

        // ---- 16-CTA group barrier + pipelined gi-readiness (tid0 only) ----
        __syncthreads();
        if (tid == 0) {
            __threadfence();
            atomicAdd(cnt, 1u);
            unsigned target = (unsigned)(s + 1) * 16u;
            while (ld_acq(cnt) < target) {}
            int s3 = (s + 2 < TT) ? (s + 2) : (TT - 1);
            int t3 = dir ? (TT - 1 - s3) : s3;
            while (ld_acq(&g_gflag[dir][t3 >> 2]) < 12u) {}
        }
        __syncthreads();

        // off-critical-path output stores
        out[((size_t)tt * BB + ebl) * 1024 + dir * HD + ej] = hn;
        if (s == TT - 1) fin[(size_t)ebl * HD + ej] = hn;
    }
}

__global__ void reset_cnt() {
    if (threadIdx.x < 128) g_cnt4[threadIdx.x] = 0u;
    if (threadIdx.x == 0) g_ticket = 0u;
    unsigned* f = &g_gflag[0][0];
    for (int i = threadIdx.x; i < 2 * MTILES; i += blockDim.x) f[i] = 0u;
}

// ========================= host launcher =========================
extern "C" void kernel_launch(void* const* d_in, const int* in_sizes, int n_in,
                              void* d_out, int out_size)
{
    (void)in_sizes; (void)n_in; (void)out_size;
    const float* x  = (const float*)d_in[0];
    const float* h0 = (const float*)d_in[1];
    float* out    = (float*)d_out;
    float* finals = out + (size_t)TT * BB * 1024;

    float *gi0, *gi1, *buf0, *buf1;
    cudaGetSymbolAddress((void**)&gi0,  g_gi0);
    cudaGetSymbolAddress((void**)&gi1,  g_gi1);
    cudaGetSymbolAddress((void**)&buf0, g_buf0);
    cudaGetSymbolAddress((void**)&buf1, g_buf1);

    const float* layin[3]   = { x, buf0, buf1 };
    float*       layout_[3] = { buf0, buf1, out };
    int Ks[3] = { 256, 1024, 1024 };

    for (int L = 0; L < 3; L++) {
        const float* wih  = (const float*)d_in[2 + L * 8 + 0];
        const float* whh  = (const float*)d_in[2 + L * 8 + 1];
        const float* bih  = (const float*)d_in[2 + L * 8 + 2];
        const float* bhh  = (const float*)d_in[2 + L * 8 + 3];
        const float* wihr = (const float*)d_in[2 + L * 8 + 4];
        const float* whhr = (const float*)d_in[2 + L * 8 + 5];
        const float* bihr = (const float*)d_in[2 + L * 8 + 6];
        const float* bhhr = (const float*)d_in[2 + L * 8 + 7];

        reset_cnt<<<1, 256>>>();
        fused_layer<<<GRID, 512, POOL_BYTES>>>(
            layin[L], wih, wihr, bih, bihr,
            whh, whhr, bhh, bhhr,
            h0 + (size_t)(2 * L) * BB * HD,
            h0 + (size_t)(2 * L + 1) * BB * HD,
            gi0, gi1,
            layout_[L],
            finals + (size_t)(2 * L) * BB * HD,
            finals + (size_t)(2 * L + 1) * BB * HD,
            Ks[L]);
    }
}

// round 16
// speedup vs baseline: 1.1527x; 1.0948x over previous
#include <cuda_runtime.h>
#include <cuda_fp16.h>
#include <cstdint>

#define TT 1024
#define BB 32
#define HD 512
#define NG 1536           // 3*HD
#define MM (TT*BB)        // 32768

#define SCAN_CTAS 64
#define GEMM_CTAS 84
#define GRID (SCAN_CTAS + GEMM_CTAS)   // 148 <= SM count -> 1 CTA/SM, co-resident
#define NTILES 12                       // NG/128
#define MTILES 256                      // MM/128
#define TOTAL_TICKETS (2 * MTILES * NTILES)

typedef unsigned long long ull;

// ---------------- device scratch (no allocations allowed) ----------------
__device__ __half g_gi0[(size_t)MM * NG];    // forward gi  (fp16, 100 MB)
__device__ __half g_gi1[(size_t)MM * NG];    // backward gi (fp16)
__device__ float g_buf0[(size_t)MM * 1024];  // layer0 output
__device__ float g_buf1[(size_t)MM * 1024];  // layer1 output
__device__ __half g_h16[2][2][BB * HD];      // ping-pong h per direction (fp16 exchange)
__device__ unsigned g_cnt4[4 * 32];          // 4 group barrier counters (128B apart)
__device__ unsigned g_ticket;                // gemm tile ticket
__device__ unsigned g_gflag[2][MTILES];      // per (dir, m-band) completed N-tiles (ready at 12)

// ========================= common helpers =========================
__device__ __forceinline__ unsigned pack2(float a, float b) {
    __half2 h = __floats2half2_rn(a, b);
    return *(unsigned*)&h;
}
__device__ __forceinline__ void mma16(float* d, const unsigned* a, const unsigned* b) {
    asm volatile("mma.sync.aligned.m16n8k16.row.col.f32.f16.f16.f32 "
                 "{%0,%1,%2,%3}, {%4,%5,%6,%7}, {%8,%9}, {%0,%1,%2,%3};"
                 : "+f"(d[0]), "+f"(d[1]), "+f"(d[2]), "+f"(d[3])
                 : "r"(a[0]), "r"(a[1]), "r"(a[2]), "r"(a[3]), "r"(b[0]), "r"(b[1]));
}
#define LDSM_X4(r0, r1, r2, r3, addr)                                            \
    asm volatile("ldmatrix.sync.aligned.m8n8.x4.shared.b16 {%0,%1,%2,%3}, [%4];" \
                 : "=r"(r0), "=r"(r1), "=r"(r2), "=r"(r3) : "r"(addr))
__device__ __forceinline__ float sigm(float x) { return 1.f / (1.f + __expf(-x)); }
__device__ __forceinline__ unsigned ld_acq(const unsigned* p) {
    unsigned v;
    asm volatile("ld.acquire.gpu.global.u32 %0, [%1];" : "=r"(v) : "l"(p) : "memory");
    return v;
}
__device__ __forceinline__ float ldcg_h(const __half* p) {
    unsigned short v;
    asm volatile("ld.global.cg.u16 %0, [%1];" : "=h"(v) : "l"(p) : "memory");
    __half h = *(__half*)&v;
    return __half2float(h);
}

#define SSH 40            // gemm smem halfs per row
#define HS 520            // scan h16 halfs per row (512 + 8 pad)
#define POOL_BYTES 43520

// =====================================================================
// FUSED layer kernel: bid < 64 -> scan consumer; bid >= 64 -> gemm producer
// =====================================================================
__global__ __launch_bounds__(512, 1) void fused_layer(
    const float* __restrict__ A,
    const float* __restrict__ W0, const float* __restrict__ W1,
    const float* __restrict__ bi0, const float* __restrict__ bi1,
    const float* __restrict__ whhF, const float* __restrict__ whhB,
    const float* __restrict__ bhhF, const float* __restrict__ bhhB,
    const float* __restrict__ h0F,  const float* __restrict__ h0B,
    __half* __restrict__ gi0, __half* __restrict__ gi1,
    float* __restrict__ out, float* __restrict__ finF, float* __restrict__ finB,
    int K)
{
    extern __shared__ char pool[];
    int bid = blockIdx.x;
    int tid = threadIdx.x, w = tid >> 5, lane = tid & 31;
    int g = lane >> 2, t = lane & 3;

    if (bid >= SCAN_CTAS) {
        // ==================== GEMM producer (512 threads, 16 warps 4m x 4n) ====================
        __half* sAB   = (__half*)pool;                       // [2][2][128*SSH]
        float*  sbias = (float*)(pool + 4 * 128 * SSH * 2);  // 128 floats
        unsigned* tick_s = (unsigned*)(pool + 4 * 128 * SSH * 2 + 512);

        int wm = (w & 3) * 32;         // warp M offset
        int wn = (w >> 2) * 32;        // warp N offset
        int grow = tid >> 2, gcol = (tid & 3) * 8;   // 512 thr: 8 floats of A and B each

        uint32_t a_off = (uint32_t)(((wm + (lane & 15)) * SSH + (lane >> 4) * 8) * 2);
        uint32_t b_off = (uint32_t)(((wn + (((lane >> 3) >= 2) ? 8 : 0) + (lane & 7)) * SSH
                                    + ((lane >> 3) & 1) * 8) * 2);
        int kT = K / 32;

        for (;;) {
            __syncthreads();            // protect smem across iterations
            if (tid == 0) *tick_s = atomicAdd(&g_ticket, 1u);
            __syncthreads();
            unsigned k = *tick_s;
            if (k >= TOTAL_TICKETS) break;
            int q = k / 24, r = k % 24;
            int dz, mt, nt;
            if (r < NTILES) { dz = 0; mt = q;              nt = r; }
            else            { dz = 1; mt = MTILES - 1 - q; nt = r - NTILES; }
            const float* W    = dz ? W1  : W0;
            const float* bias = dz ? bi1 : bi0;
            __half*      C    = dz ? gi1 : gi0;
            int m0 = mt * 128, n0 = nt * 128;

            if (tid < 128) sbias[tid] = bias[n0 + tid];

            const float* Ag = A + (size_t)(m0 + grow) * K + gcol;
            const float* Wg = W + (size_t)(n0 + grow) * K + gcol;

            float acc[2][4][4];
#pragma unroll
            for (int mtt = 0; mtt < 2; mtt++)
#pragma unroll
                for (int ntt = 0; ntt < 4; ntt++)
#pragma unroll
                    for (int e = 0; e < 4; e++) acc[mtt][ntt][e] = 0.f;

            float4 av0, av1, wv0, wv1;
            av0 = *(const float4*)(Ag);     av1 = *(const float4*)(Ag + 4);
            wv0 = *(const float4*)(Wg);     wv1 = *(const float4*)(Wg + 4);
            {
                __half* dA = sAB + 0 * 128 * SSH;
                __half* dB = sAB + 1 * 128 * SSH;
                uint4 ua = { pack2(av0.x, av0.y), pack2(av0.z, av0.w), pack2(av1.x, av1.y), pack2(av1.z, av1.w) };
                uint4 uw = { pack2(wv0.x, wv0.y), pack2(wv0.z, wv0.w), pack2(wv1.x, wv1.y), pack2(wv1.z, wv1.w) };
                *(uint4*)&dA[grow * SSH + gcol] = ua;
                *(uint4*)&dB[grow * SSH + gcol] = uw;
            }
            __syncthreads();

            for (int s = 0; s < kT; s++) {
                int bb = s & 1;
                if (s + 1 < kT) {
                    int k0 = (s + 1) * 32;
                    av0 = *(const float4*)(Ag + k0);     av1 = *(const float4*)(Ag + k0 + 4);
                    wv0 = *(const float4*)(Wg + k0);     wv1 = *(const float4*)(Wg + k0 + 4);
                }
                uint32_t a_u = (uint32_t)__cvta_generic_to_shared(sAB + (bb * 2 + 0) * 128 * SSH) + a_off;
                uint32_t b_u = (uint32_t)__cvta_generic_to_shared(sAB + (bb * 2 + 1) * 128 * SSH) + b_off;
#pragma unroll
                for (int kk = 0; kk < 2; kk++) {
                    uint32_t kb = (uint32_t)(kk * 32);
                    unsigned afr[2][4], bfr[4][2];
                    LDSM_X4(afr[0][0], afr[0][1], afr[0][2], afr[0][3], a_u + kb);
                    LDSM_X4(afr[1][0], afr[1][1], afr[1][2], afr[1][3], a_u + 16 * SSH * 2 + kb);
                    LDSM_X4(bfr[0][0], bfr[0][1], bfr[1][0], bfr[1][1], b_u + kb);
                    LDSM_X4(bfr[2][0], bfr[2][1], bfr[3][0], bfr[3][1], b_u + 16 * SSH * 2 + kb);
#pragma unroll
                    for (int mtt = 0; mtt < 2; mtt++)
#pragma unroll
                        for (int ntt = 0; ntt < 4; ntt++)
                            mma16(acc[mtt][ntt], afr[mtt], bfr[ntt]);
                }
                if (s + 1 < kT) {
                    int nb = bb ^ 1;
                    __half* dA = sAB + (nb * 2 + 0) * 128 * SSH;
                    __half* dB = sAB + (nb * 2 + 1) * 128 * SSH;
                    uint4 ua = { pack2(av0.x, av0.y), pack2(av0.z, av0.w), pack2(av1.x, av1.y), pack2(av1.z, av1.w) };
                    uint4 uw = { pack2(wv0.x, wv0.y), pack2(wv0.z, wv0.w), pack2(wv1.x, wv1.y), pack2(wv1.z, wv1.w) };
                    *(uint4*)&dA[grow * SSH + gcol] = ua;
                    *(uint4*)&dB[grow * SSH + gcol] = uw;
                }
                __syncthreads();
            }

            // epilogue: pack to fp16 (halves gi traffic)
#pragma unroll
            for (int mtt = 0; mtt < 2; mtt++) {
                int m = m0 + wm + mtt * 16 + g;
#pragma unroll
                for (int ntt = 0; ntt < 4; ntt++) {
                    int nl = wn + ntt * 8 + 2 * t;
                    float b0 = sbias[nl], b1 = sbias[nl + 1];
                    __half2 p0 = __floats2half2_rn(acc[mtt][ntt][0] + b0, acc[mtt][ntt][1] + b1);
                    __half2 p1 = __floats2half2_rn(acc[mtt][ntt][2] + b0, acc[mtt][ntt][3] + b1);
                    *(__half2*)&C[(size_t)m * NG + n0 + nl]       = p0;
                    *(__half2*)&C[(size_t)(m + 8) * NG + n0 + nl] = p1;
                }
            }
            __threadfence();                     // make gi stores visible before flag
            if (tid == 0) atomicAdd(&g_gflag[dz][mt], 1u);
        }
        return;
    }

    // ==================== SCAN consumer (R13 structure; fp16 gi; gated band poll) ====================
    __half* h16 = (__half*)pool;                 // 16 x HS
    float*  sg  = (float*)(pool + 16 * HS * 2);  // [3][16][34]

    int dir = bid >> 5, cid = bid & 31, bhalf = cid & 1, jblk = cid >> 1;
    unsigned* cnt = &g_cnt4[(dir * 2 + bhalf) * 32];

    const __half* gi = dir ? gi1  : gi0;
    const float* whh = dir ? whhB : whhF;
    const float* bhh = dir ? bhhB : bhhF;
    const float* h0  = dir ? h0B  : h0F;
    float* fin = dir ? finB : finF;

    int eb = tid >> 5, ejj = tid & 31;           // (batch 0-15, local j 0-31)
    int ej  = jblk * 32 + ejj;
    int ebl = bhalf * 16 + eb;
    float bhr = bhh[ej], bhz = bhh[HD + ej], bhn = bhh[2 * HD + ej];
    float hp = __ldcg(&h0[(size_t)ebl * HD + ej]);

    unsigned bw[32][2];
    if (w < 12) {
        int nl = w * 8 + g;
        int gate = nl >> 5, jj = nl & 31;
        const float* Wr = whh + (size_t)(gate * HD + jblk * 32 + jj) * HD;
#pragma unroll
        for (int kk = 0; kk < 32; kk++) {
            int k0 = kk * 16;
            bw[kk][0] = pack2(Wr[k0 + 2 * t],     Wr[k0 + 2 * t + 1]);
            bw[kk][1] = pack2(Wr[k0 + 2 * t + 8], Wr[k0 + 2 * t + 9]);
        }
    }

    uint32_t h16a = (uint32_t)__cvta_generic_to_shared(h16);
    uint32_t lma = h16a + (uint32_t)(((lane & 15) * HS + (lane >> 4) * 8) * 2);

    // pre-loop: wait gi bands for steps 0 and 1
    if (tid == 0) {
        int ta = dir ? (TT - 1) : 0;
        int tb = dir ? (TT - 2) : 1;
        while (ld_acq(&g_gflag[dir][ta >> 2]) < 12u) {}
        while (ld_acq(&g_gflag[dir][tb >> 2]) < 12u) {}
    }
    __syncthreads();

    float gir, giz, gin;
    {
        int t0 = dir ? (TT - 1) : 0;
        size_t gb = ((size_t)t0 * BB + ebl) * NG;
        gir = ldcg_h(&gi[gb + ej]);
        giz = ldcg_h(&gi[gb + HD + ej]);
        gin = ldcg_h(&gi[gb + 2 * HD + ej]);
    }

    for (int s = 0; s < TT; s++) {
        int tt = dir ? (TT - 1 - s) : s;

        // ---- stage h (16 b x 512 fp16) ----
        if (s == 0) {
            const float4* src = (const float4*)(h0 + (size_t)ebl * HD + ejj * 16);
            float4 v0 = __ldcg(src + 0), v1 = __ldcg(src + 1), v2 = __ldcg(src + 2), v3 = __ldcg(src + 3);
            uint4 u0 = { pack2(v0.x, v0.y), pack2(v0.z, v0.w), pack2(v1.x, v1.y), pack2(v1.z, v1.w) };
            uint4 u1 = { pack2(v2.x, v2.y), pack2(v2.z, v2.w), pack2(v3.x, v3.y), pack2(v3.z, v3.w) };
            *(uint4*)&h16[eb * HS + ejj * 16]     = u0;
            *(uint4*)&h16[eb * HS + ejj * 16 + 8] = u1;
        } else {
            const uint4* src = (const uint4*)(g_h16[dir][s & 1] + (size_t)ebl * HD);
            *(uint4*)&h16[eb * HS + ejj * 8]        = __ldcg(src + ejj);
            *(uint4*)&h16[eb * HS + (ejj + 32) * 8] = __ldcg(src + ejj + 32);
        }
        __syncthreads();

        // ---- recurrent GEMM: 12 warps x (32 ldmatrix + 32 mma) ----
        if (w < 12) {
            float acc[4] = { 0.f, 0.f, 0.f, 0.f };
#pragma unroll
            for (int kk = 0; kk < 32; kk++) {
                unsigned a0, a1, a2, a3;
                LDSM_X4(a0, a1, a2, a3, lma + kk * 32);
                unsigned af[4] = { a0, a1, a2, a3 };
                mma16(acc, af, bw[kk]);
            }
            int nl = w * 8 + 2 * t;
            int gate = nl >> 5, jj2 = nl & 31;
            float* p = &sg[gate * 544 + g * 34 + jj2];
            *(float2*)p            = make_float2(acc[0], acc[1]);
            *(float2*)(p + 8 * 34) = make_float2(acc[2], acc[3]);
        }
        __syncthreads();

        // ---- gate math (1 thread = 1 (b,j)) ----
        float gr = sg[0 * 544 + eb * 34 + ejj];
        float gz = sg[1 * 544 + eb * 34 + ejj];
        float gn = sg[2 * 544 + eb * 34 + ejj];
        float r  = sigm(gir + gr + bhr);
        float z  = sigm(giz + gz + bhz);
        float n  = tanhf(gin + r * (gn + bhn));
        float hn = (1.f - z) * n + z * hp;
        hp = hn;

        // publish h (fp16)
        g_h16[dir][(s + 1) & 1][(size_t)ebl * HD + ej] = __float2half_rn(hn);

        // prefetch next gi (readiness ensured one step ago; fp16 -> 6 B/thread)
        {
            int s2 = (s + 1 < TT) ? (s + 1) : s;
            int t2 = dir ? (TT - 1 - s2) : s2;
            size_t gb = ((size_t)t2 * BB + ebl) * NG;
            gir = ldcg_h(&gi[gb + ej]);
            giz = ldcg_h(&gi[gb + HD + ej]);
            gin = ldcg_h(&gi[gb + 2 * HD + ej]);
        }

        // ---- 16-CTA group barrier + band poll only at band boundaries ----
        __syncthreads();
        if (tid == 0) {
            __threadfence();
            atomicAdd(cnt, 1u);
            unsigned target = (unsigned)(s + 1) * 16u;
            while (ld_acq(cnt) < target) {}
            int s3 = s + 2;
            if (s3 < TT && (s3 & 3) == 0) {      // gi band changes every 4 steps (both dirs)
                int t3 = dir ? (TT - 1 - s3) : s3;
                while (ld_acq(&g_gflag[dir][t3 >> 2]) < 12u) {}
            }
        }
        __syncthreads();

        // off-critical-path output stores
        out[((size_t)tt * BB + ebl) * 1024 + dir * HD + ej] = hn;
        if (s == TT - 1) fin[(size_t)ebl * HD + ej] = hn;
    }
}

__global__ void reset_cnt() {
    if (threadIdx.x < 128) g_cnt4[threadIdx.x] = 0u;
    if (threadIdx.x == 0) g_ticket = 0u;
    unsigned* f = &g_gflag[0][0];
    for (int i = threadIdx.x; i < 2 * MTILES; i += blockDim.x) f[i] = 0u;
}

// ========================= host launcher =========================
extern "C" void kernel_launch(void* const* d_in, const int* in_sizes, int n_in,
                              void* d_out, int out_size)
{
    (void)in_sizes; (void)n_in; (void)out_size;
    const float* x  = (const float*)d_in[0];
    const float* h0 = (const float*)d_in[1];
    float* out    = (float*)d_out;
    float* finals = out + (size_t)TT * BB * 1024;

    __half *gi0, *gi1;
    float *buf0, *buf1;
    cudaGetSymbolAddress((void**)&gi0,  g_gi0);
    cudaGetSymbolAddress((void**)&gi1,  g_gi1);
    cudaGetSymbolAddress((void**)&buf0, g_buf0);
    cudaGetSymbolAddress((void**)&buf1, g_buf1);

    const float* layin[3]   = { x, buf0, buf1 };
    float*       layout_[3] = { buf0, buf1, out };
    int Ks[3] = { 256, 1024, 1024 };

    for (int L = 0; L < 3; L++) {
        const float* wih  = (const float*)d_in[2 + L * 8 + 0];
        const float* whh  = (const float*)d_in[2 + L * 8 + 1];
        const float* bih  = (const float*)d_in[2 + L * 8 + 2];
        const float* bhh  = (const float*)d_in[2 + L * 8 + 3];
        const float* wihr = (const float*)d_in[2 + L * 8 + 4];
        const float* whhr = (const float*)d_in[2 + L * 8 + 5];
        const float* bihr = (const float*)d_in[2 + L * 8 + 6];
        const float* bhhr = (const float*)d_in[2 + L * 8 + 7];

        reset_cnt<<<1, 256>>>();
        fused_layer<<<GRID, 512, POOL_BYTES>>>(
            layin[L], wih, wihr, bih, bihr,
            whh, whhr, bhh, bhhr,
            h0 + (size_t)(2 * L) * BB * HD,
            h0 + (size_t)(2 * L + 1) * BB * HD,
            gi0, gi1,
            layout_[L],
            finals + (size_t)(2 * L) * BB * HD,
            finals + (size_t)(2 * L + 1) * BB * HD,
            Ks[L]);
    }
}